// round 14
// baseline (speedup 1.0000x reference)
#include <cuda_runtime.h>
#include <cuda_fp16.h>
#include <cstdint>

// Problem constants
#define BB 32
#define NN 1024
#define IN_DIM 64
#define HID 128
#define OUTD 64        // 2*LAT
#define NUM_LAYERS 3

// fp16 range management (all powers of two => exact):
//   hT buffers store h * SH (SH=1/16); Tbuf stores T/1024; h3 stores h3 * 2^-14
#define SH_F    0.0625f           // 2^-4
#define ST2_F   0.015625f         // 2^-6
#define UNSC_F  1024.0f           // 1/(SH*ST2)
#define SP_F    6.103515625e-05f  // 2^-14
#define UNSC2_F 16384.0f          // 1/SP

// Scratch (device globals; no allocations allowed)
__device__ __half g_adjh[(size_t)BB * NN * NN];       // 67 MB fp16 adjacency (written by layer 1)
__device__ __half g_hT[2][(size_t)BB * HID * NN];     // ping-pong transposed activations (scaled SH)
__device__ __half g_xh[(size_t)BB * NN * IN_DIM];     // fp16 node features
__device__ float  g_rowsum[BB * NN];                  // per-node adjacency row sums (written by layer 1)
__device__ __half g_WlTh[NUM_LAYERS * HID * HID];     // Wl transposed, fp16
__device__ __half g_WembTh[HID * IN_DIM];             // Wemb transposed, fp16
__device__ __half g_WprojTh[2 * OUTD * 64];           // WprojT in 2 k-chunks, fp16

// ============================================================================
// Helpers
// ============================================================================
__device__ __forceinline__ uint32_t smem_u32(const void* p) {
    uint32_t a;
    asm("{ .reg .u64 t; cvta.to.shared.u64 t, %1; cvt.u32.u64 %0, t; }"
        : "=r"(a) : "l"(p));
    return a;
}

__device__ __forceinline__ uint32_t pack_h2(float a, float b) {
    __half2 h = __floats2half2_rn(a, b);
    return *reinterpret_cast<uint32_t*>(&h);
}

__device__ __forceinline__ void mma_f16(float c[4],
                                        uint32_t a0, uint32_t a1, uint32_t a2, uint32_t a3,
                                        uint32_t b0, uint32_t b1) {
    asm volatile(
        "mma.sync.aligned.m16n8k16.row.col.f32.f16.f16.f32 "
        "{%0,%1,%2,%3}, {%4,%5,%6,%7}, {%8,%9}, {%0,%1,%2,%3};"
        : "+f"(c[0]), "+f"(c[1]), "+f"(c[2]), "+f"(c[3])
        : "r"(a0), "r"(a1), "r"(a2), "r"(a3), "r"(b0), "r"(b1));
}

#define LDMX4(r0, r1, r2, r3, addr) \
    asm volatile("ldmatrix.sync.aligned.m8n8.x4.shared.b16 {%0,%1,%2,%3}, [%4];" \
                 : "=r"(r0), "=r"(r1), "=r"(r2), "=r"(r3) : "r"(addr))

#define CP_ASYNC16(dst, src) \
    asm volatile("cp.async.cg.shared.global [%0], [%1], 16;" :: "r"(dst), "l"(src))
#define CP_COMMIT() asm volatile("cp.async.commit_group;" ::: "memory")
#define CP_WAIT1()  asm volatile("cp.async.wait_group 1;" ::: "memory")
#define CP_WAIT0()  asm volatile("cp.async.wait_group 0;" ::: "memory")

#define STS64(addr, x, y) \
    asm volatile("st.shared.v2.u32 [%0], {%1,%2};" :: "r"(addr), "r"(x), "r"(y) : "memory")

// Load one 16KB fp16 tile (128 rows x 64 halves, 128B rows) via cp.async.
// 16B word q of row r stored at word q ^ (r&7): conflict-free fill + ldmatrix.
__device__ __forceinline__ void load_tile16(
    uint32_t dst, const __half* __restrict__ src, int rowstride_h, int tid)
{
#pragma unroll
    for (int i = 0; i < 4; i++) {
        int idx = tid + i * 256;             // 0..1023
        int row = idx >> 3;                  // 0..127
        int q   = idx & 7;                   // 16B word
        CP_ASYNC16(dst + row * 128 + ((q ^ (row & 7)) << 4),
                   src + (size_t)row * rowstride_h + q * 8);
    }
}

// 64-row variant (8KB tile)
__device__ __forceinline__ void load_tile8(
    uint32_t dst, const __half* __restrict__ src, int rowstride_h, int tid)
{
#pragma unroll
    for (int i = 0; i < 2; i++) {
        int idx = tid + i * 256;
        int row = idx >> 3;
        int q   = idx & 7;
        CP_ASYNC16(dst + row * 128 + ((q ^ (row & 7)) << 4),
                   src + (size_t)row * rowstride_h + q * 8);
    }
}

// ============================================================================
// Prep kernels
// ============================================================================
__global__ void prep_weights(const float* __restrict__ Wl,
                             const float* __restrict__ Wemb,
                             const float* __restrict__ Wproj,
                             __half* __restrict__ wlt,
                             __half* __restrict__ wembT,
                             __half* __restrict__ wpT)
{
    int bid = blockIdx.x;
    if (bid < NUM_LAYERS) {
        const float* W = Wl + (size_t)bid * HID * HID;
        __half* T = wlt + (size_t)bid * HID * HID;
        for (int i = threadIdx.x; i < HID * HID; i += blockDim.x) {
            int n2 = i >> 7, n = i & 127;
            T[i] = __float2half(W[n * HID + n2]);
        }
    } else if (bid == NUM_LAYERS) {
        for (int i = threadIdx.x; i < HID * IN_DIM; i += blockDim.x) {
            int o = i >> 6, i2 = i & 63;
            wembT[i] = __float2half(Wemb[i2 * HID + o]);
        }
    } else {
        for (int i = threadIdx.x; i < 2 * OUTD * 64; i += blockDim.x) {
            int c = i >> 12, o = (i >> 6) & 63, f = i & 63;
            wpT[i] = __float2half(Wproj[(64 * c + f) * OUTD + o]);
        }
    }
}

// x fp32 -> fp16 (streaming)
__global__ __launch_bounds__(256) void conv_x(
    const float* __restrict__ x, __half* __restrict__ xh)
{
    int idx = blockIdx.x * 256 + threadIdx.x;
    float4 v = *reinterpret_cast<const float4*>(x + (size_t)idx * 4);
    union { __half2 h[2]; uint2 u; } pk;
    pk.h[0] = __floats2half2_rn(v.x, v.y);
    pk.h[1] = __floats2half2_rn(v.z, v.w);
    *reinterpret_cast<uint2*>(xh + (size_t)idx * 4) = pk.u;
}

// ============================================================================
// Shared fragment-map
// ============================================================================
struct FragMap {
    uint32_t Qa[4];
    uint32_t Qb[2];
    int m_warp, n_warp, g, tg;
};

__device__ __forceinline__ FragMap make_fragmap(int tid, int nwarp_span) {
    FragMap f;
    const int wid = tid >> 5;
    const int lid = tid & 31;
    f.g  = lid >> 2;
    f.tg = lid & 3;
    f.m_warp = (wid & 1) * 64;
    f.n_warp = (wid >> 1) * nwarp_span;
    const int xr  = lid & 7;
    const int rAo = ((lid >> 3) & 1) * 8;
    const int w0A = (lid >> 4) & 1;
#pragma unroll
    for (int mt = 0; mt < 4; mt++) {
        int r = f.m_warp + mt * 16 + rAo + xr;
        f.Qa[mt] = (uint32_t)(r * 128 + ((w0A ^ xr) << 4));
    }
    const int w0B = (lid >> 3) & 1;
    const int ntB = (lid >> 4) & 1;
#pragma unroll
    for (int p = 0; p < 2; p++) {
        int rn = f.n_warp + (p * 2 + ntB) * 8 + xr;
        f.Qb[p] = (uint32_t)(rn * 128 + ((w0B ^ xr) << 4));
    }
    return f;
}

// ============================================================================
// Embed: hT0 = (x @ Wemb)^T * SH
// ============================================================================
#define ETILE 16384
#define HBUF_STRIDE 136
#define EHBUF_OFF (2 * ETILE)
#define SMTOT_E (EHBUF_OFF + 128 * HBUF_STRIDE * 2)    // 67584

__global__ __launch_bounds__(256, 2) void embed_mma(
    const __half* __restrict__ xh, const __half* __restrict__ wembT,
    __half* __restrict__ hTout)
{
    extern __shared__ __align__(1024) char smem[];
    const uint32_t sb = smem_u32(smem);
    const int tid = threadIdx.x;
    const int row0 = blockIdx.x * 128;
    const int b = row0 >> 10;
    const int node0 = row0 & (NN - 1);

    FragMap f = make_fragmap(tid, 32);

    load_tile16(sb,         xh + (size_t)row0 * IN_DIM, IN_DIM, tid);
    load_tile16(sb + ETILE, wembT, IN_DIM, tid);
    CP_COMMIT();

    float acc[4][4][4];
#pragma unroll
    for (int mt = 0; mt < 4; mt++)
#pragma unroll
        for (int nt = 0; nt < 4; nt++)
#pragma unroll
            for (int r = 0; r < 4; r++) acc[mt][nt][r] = 0.f;

    CP_WAIT0();
    __syncthreads();

#pragma unroll
    for (int kk = 0; kk < 4; kk++) {
        const uint32_t kx = (uint32_t)kk << 5;
        uint32_t bf[4][2];
        LDMX4(bf[0][0], bf[0][1], bf[1][0], bf[1][1], (sb + ETILE + f.Qb[0]) ^ kx);
        LDMX4(bf[2][0], bf[2][1], bf[3][0], bf[3][1], (sb + ETILE + f.Qb[1]) ^ kx);
#pragma unroll
        for (int mt = 0; mt < 4; mt++) {
            uint32_t a0, a1, a2, a3;
            LDMX4(a0, a1, a2, a3, (sb + f.Qa[mt]) ^ kx);
#pragma unroll
            for (int nt = 0; nt < 4; nt++)
                mma_f16(acc[mt][nt], a0, a1, a2, a3, bf[nt][0], bf[nt][1]);
        }
    }

    __half* hb = reinterpret_cast<__half*>(smem + EHBUF_OFF);
#pragma unroll
    for (int mt = 0; mt < 4; mt++) {
        int mr = f.m_warp + mt * 16 + f.g;
#pragma unroll
        for (int nt = 0; nt < 4; nt++) {
            int col = f.n_warp + nt * 8 + 2 * f.tg;
            hb[(col)     * HBUF_STRIDE + mr]     = __float2half(acc[mt][nt][0] * SH_F);
            hb[(col + 1) * HBUF_STRIDE + mr]     = __float2half(acc[mt][nt][1] * SH_F);
            hb[(col)     * HBUF_STRIDE + mr + 8] = __float2half(acc[mt][nt][2] * SH_F);
            hb[(col + 1) * HBUF_STRIDE + mr + 8] = __float2half(acc[mt][nt][3] * SH_F);
        }
    }
    __syncthreads();
#pragma unroll
    for (int p = 0; p < 8; p++) {
        int idx = tid + p * 256;
        int c = idx >> 4, u = idx & 15;
        uint4 v = *reinterpret_cast<const uint4*>(hb + c * HBUF_STRIDE + u * 8);
        *reinterpret_cast<uint4*>(
            hTout + ((size_t)(b * HID + c)) * NN + node0 + u * 8) = v;
    }
}

// ============================================================================
// Proj: out = (h3 @ Wproj + bproj) * mask
// ============================================================================
#define SMTOT_P (2 * ETILE + 2 * 8192)     // 49152

__global__ __launch_bounds__(256, 2) void proj_mma(
    const __half* __restrict__ h3h, const __half* __restrict__ wpT,
    const float* __restrict__ bproj, const float* __restrict__ mask,
    float* __restrict__ out)
{
    extern __shared__ __align__(1024) char smem[];
    const uint32_t sb = smem_u32(smem);
    const int tid = threadIdx.x;
    const int row0 = blockIdx.x * 128;

    FragMap f = make_fragmap(tid, 16);

    load_tile16(sb,          h3h + (size_t)row0 * HID,      HID, tid);
    load_tile16(sb + ETILE,  h3h + (size_t)row0 * HID + 64, HID, tid);
    load_tile8 (sb + 2 * ETILE,        wpT,             64, tid);
    load_tile8 (sb + 2 * ETILE + 8192, wpT + OUTD * 64, 64, tid);
    CP_COMMIT();

    float acc[4][2][4];
#pragma unroll
    for (int mt = 0; mt < 4; mt++)
#pragma unroll
        for (int nt = 0; nt < 2; nt++)
#pragma unroll
            for (int r = 0; r < 4; r++) acc[mt][nt][r] = 0.f;

    CP_WAIT0();
    __syncthreads();

#pragma unroll
    for (int ch = 0; ch < 2; ch++) {
        const uint32_t sA = sb + ch * ETILE;
        const uint32_t sW = sb + 2 * ETILE + ch * 8192;
#pragma unroll
        for (int kk = 0; kk < 4; kk++) {
            const uint32_t kx = (uint32_t)kk << 5;
            uint32_t bf[2][2];
            LDMX4(bf[0][0], bf[0][1], bf[1][0], bf[1][1], (sW + f.Qb[0]) ^ kx);
#pragma unroll
            for (int mt = 0; mt < 4; mt++) {
                uint32_t a0, a1, a2, a3;
                LDMX4(a0, a1, a2, a3, (sA + f.Qa[mt]) ^ kx);
#pragma unroll
                for (int nt = 0; nt < 2; nt++)
                    mma_f16(acc[mt][nt], a0, a1, a2, a3, bf[nt][0], bf[nt][1]);
            }
        }
    }

#pragma unroll
    for (int mt = 0; mt < 4; mt++) {
        int mr = row0 + f.m_warp + mt * 16 + f.g;
        float m0 = mask[mr], m1 = mask[mr + 8];
#pragma unroll
        for (int nt = 0; nt < 2; nt++) {
            int col = f.n_warp + nt * 8 + 2 * f.tg;
            float b0 = bproj[col], b1 = bproj[col + 1];
            float2 p0, p1;
            p0.x = fmaf(acc[mt][nt][0], UNSC2_F, b0) * m0;
            p0.y = fmaf(acc[mt][nt][1], UNSC2_F, b1) * m0;
            p1.x = fmaf(acc[mt][nt][2], UNSC2_F, b0) * m1;
            p1.y = fmaf(acc[mt][nt][3], UNSC2_F, b1) * m1;
            *reinterpret_cast<float2*>(&out[(size_t)mr * OUTD + col])       = p0;
            *reinterpret_cast<float2*>(&out[(size_t)(mr + 8) * OUTD + col]) = p1;
        }
    }
}

// ============================================================================
// Fused GCN layer.
//   CONVERT=true (layer 1): A read as fp32 via reg-staged __ldcs, converted to
//     fp16 (STS swizzled smem + STG g_adjh), rowsums accumulated in-register.
//   CONVERT=false: A via cp.async from g_adjh (R11 register-pipelined loop).
//   acc = adjh @ (h*SH)^T ; Tbuf = acc/64 ; h' = relu(1024*(Tbuf@Wl)+rs*bl)
// ============================================================================
#define ST 3
#define BKH 64
#define NITH (NN / BKH)            // 16
#define TILE16 16384
#define HBUF_OFF (4 * TILE16)
#define RSM_OFF (HBUF_OFF + 128 * HBUF_STRIDE * 2)     // 100352
#define SMTOT (RSM_OFF + 512)                          // 100864 B

template<bool LAST, bool CONVERT>
__global__ __launch_bounds__(256, 2) void adj_layer(
    const float* __restrict__ adjf, __half* __restrict__ adjhw,
    const __half* __restrict__ adjh, const __half* __restrict__ hTin,
    const __half* __restrict__ wlt,  const float* __restrict__ bl,
    const float* __restrict__ rowsum_in, float* __restrict__ rowsum_out,
    __half* __restrict__ hTout, __half* __restrict__ h3out)
{
    extern __shared__ __align__(1024) char smem[];
    const uint32_t sb = smem_u32(smem);
    const int tid = threadIdx.x;
    const int lid = tid & 31;
    const int b    = blockIdx.y;
    const int row0 = blockIdx.x * 128;

    FragMap f = make_fragmap(tid, 32);
    const int m_warp = f.m_warp, n_warp = f.n_warp, g = f.g, tg = f.tg;

    const __half* Bb = hTin + (size_t)b * HID * NN;
    float* rsm = reinterpret_cast<float*>(smem + RSM_OFF);

    float acc[4][4][4];
#pragma unroll
    for (int mt = 0; mt < 4; mt++)
#pragma unroll
        for (int nt = 0; nt < 4; nt++)
#pragma unroll
            for (int r = 0; r < 4; r++) acc[mt][nt][r] = 0.f;

    if (CONVERT) {
        // ---- layer-1 mainloop: fp32 A -> convert -> fp16 smem/global ----
        const int a16 = tid >> 4;      // base row 0..15
        const int f4  = tid & 15;      // float4 column within 256B row
        const int w16 = f4 >> 1;       // 16B word
        const int sub = (f4 & 1) * 8;
        const float* pAf = adjf + (size_t)b * NN * NN
                         + (size_t)(row0 + a16) * NN + 4 * f4;
        __half* pAh = adjhw + (size_t)b * NN * NN
                    + (size_t)(row0 + a16) * NN + 4 * f4;

        float4 R[8];
        float ps[8];
#pragma unroll
        for (int j = 0; j < 8; j++) ps[j] = 0.f;

        // B preload chunks 0,1
#pragma unroll
        for (int p = 0; p < 2; p++) {
            load_tile16(sb + (ST + p) * TILE16, Bb + p * BKH, NN, tid);
            CP_COMMIT();
        }
        // A prologue: LDG chunk0 -> STS slot0 -> LDG chunk1
#pragma unroll
        for (int j = 0; j < 8; j++)
            R[j] = __ldcs(reinterpret_cast<const float4*>(pAf + (size_t)(16 * j) * NN));
#pragma unroll
        for (int j = 0; j < 8; j++) {
            int row = a16 + 16 * j;
            float4 v = R[j];
            ps[j] += v.x + v.y + v.z + v.w;
            uint32_t px = pack_h2(v.x, v.y), py = pack_h2(v.z, v.w);
            STS64(sb + row * 128 + ((w16 ^ (row & 7)) << 4) + sub, px, py);
            uint2 pk = make_uint2(px, py);
            *reinterpret_cast<uint2*>(pAh + (size_t)(16 * j) * NN) = pk;
        }
#pragma unroll
        for (int j = 0; j < 8; j++)
            R[j] = __ldcs(reinterpret_cast<const float4*>(pAf + (size_t)(16 * j) * NN + 64));

        for (int it = 0; it < NITH; it++) {
            const int s = it % ST;
            CP_WAIT1();
            __syncthreads();

            // STS chunk it+1 (from R), rowsum, STG fp16
            if (it + 1 < NITH) {
                const uint32_t slotA = sb + ((it + 1) % ST) * TILE16;
                const int coff = (it + 1) * BKH;
#pragma unroll
                for (int j = 0; j < 8; j++) {
                    int row = a16 + 16 * j;
                    float4 v = R[j];
                    ps[j] += v.x + v.y + v.z + v.w;
                    uint32_t px = pack_h2(v.x, v.y), py = pack_h2(v.z, v.w);
                    STS64(slotA + row * 128 + ((w16 ^ (row & 7)) << 4) + sub, px, py);
                    uint2 pk = make_uint2(px, py);
                    *reinterpret_cast<uint2*>(pAh + (size_t)(16 * j) * NN + coff) = pk;
                }
            }
            // LDG chunk it+2
            if (it + 2 < NITH) {
                const int coff = (it + 2) * BKH;
#pragma unroll
                for (int j = 0; j < 8; j++)
                    R[j] = __ldcs(reinterpret_cast<const float4*>(
                        pAf + (size_t)(16 * j) * NN + coff));
                load_tile16(sb + (ST + (it + 2) % ST) * TILE16,
                            Bb + (size_t)(it + 2) * BKH, NN, tid);
            }
            CP_COMMIT();

            // MMA on chunk it (R9-style)
            const uint32_t sA = sb + s * TILE16;
            const uint32_t sB = sb + (ST + s) * TILE16;
#pragma unroll
            for (int kk = 0; kk < 4; kk++) {
                const uint32_t kx = (uint32_t)kk << 5;
                uint32_t bf[4][2];
                LDMX4(bf[0][0], bf[0][1], bf[1][0], bf[1][1], (sB + f.Qb[0]) ^ kx);
                LDMX4(bf[2][0], bf[2][1], bf[3][0], bf[3][1], (sB + f.Qb[1]) ^ kx);
#pragma unroll
                for (int mt = 0; mt < 4; mt++) {
                    uint32_t a0, a1, a2, a3;
                    LDMX4(a0, a1, a2, a3, (sA + f.Qa[mt]) ^ kx);
#pragma unroll
                    for (int nt = 0; nt < 4; nt++)
                        mma_f16(acc[mt][nt], a0, a1, a2, a3, bf[nt][0], bf[nt][1]);
                }
            }
        }

        // rowsum: 16-lane shfl reduce (lanes 0-15 / 16-31 are row groups)
#pragma unroll
        for (int j = 0; j < 8; j++) {
#pragma unroll
            for (int o = 8; o >= 1; o >>= 1)
                ps[j] += __shfl_xor_sync(0xFFFFFFFFu, ps[j], o);
        }
        if ((lid & 15) == 0) {
#pragma unroll
            for (int j = 0; j < 8; j++) {
                int row = a16 + 16 * j;
                rsm[row] = ps[j];
                rowsum_out[b * NN + row0 + row] = ps[j];
            }
        }
    } else {
        // ---- layers 2-3 mainloop: R11 register-pipelined fp16 path ----
        const __half* Ab = adjh + (size_t)b * NN * NN + (size_t)row0 * NN;
#pragma unroll
        for (int p = 0; p < 2; p++) {
            load_tile16(sb + p * TILE16, Ab + p * BKH, NN, tid);
            load_tile16(sb + (ST + p) * TILE16, Bb + p * BKH, NN, tid);
            CP_COMMIT();
        }

        for (int it = 0; it < NITH; it++) {
            const int s = it % ST;
            CP_WAIT1();
            __syncthreads();

            const uint32_t sA = sb + s * TILE16;
            const uint32_t sB = sb + (ST + s) * TILE16;

            uint32_t bf[2][4][2];
            uint32_t af[2][4];
            LDMX4(bf[0][0][0], bf[0][0][1], bf[0][1][0], bf[0][1][1], sB + f.Qb[0]);
            LDMX4(bf[0][2][0], bf[0][2][1], bf[0][3][0], bf[0][3][1], sB + f.Qb[1]);
            LDMX4(af[0][0], af[0][1], af[0][2], af[0][3], sA + f.Qa[0]);

#pragma unroll
            for (int kk = 0; kk < 4; kk++) {
                const uint32_t kx  = (uint32_t)kk << 5;
                const uint32_t kxn = (uint32_t)(kk + 1) << 5;
                const int cb = kk & 1, nb = cb ^ 1;
                if (kk < 3) {
                    LDMX4(bf[nb][0][0], bf[nb][0][1], bf[nb][1][0], bf[nb][1][1],
                          (sB + f.Qb[0]) ^ kxn);
                    LDMX4(bf[nb][2][0], bf[nb][2][1], bf[nb][3][0], bf[nb][3][1],
                          (sB + f.Qb[1]) ^ kxn);
                }
#pragma unroll
                for (int mt = 0; mt < 4; mt++) {
                    const int ca = mt & 1, na = ca ^ 1;
                    if (mt < 3) {
                        LDMX4(af[na][0], af[na][1], af[na][2], af[na][3],
                              (sA + f.Qa[mt + 1]) ^ kx);
                    } else if (kk < 3) {
                        LDMX4(af[na][0], af[na][1], af[na][2], af[na][3],
                              (sA + f.Qa[0]) ^ kxn);
                    }
#pragma unroll
                    for (int nt = 0; nt < 4; nt++)
                        mma_f16(acc[mt][nt], af[ca][0], af[ca][1], af[ca][2], af[ca][3],
                                bf[cb][nt][0], bf[cb][nt][1]);
                }
                if (kk == 0) {
                    if (it + 2 < NITH) {
                        const int sl = (it + 2) % ST;
                        load_tile16(sb + sl * TILE16, Ab + (it + 2) * BKH, NN, tid);
                        load_tile16(sb + (ST + sl) * TILE16, Bb + (it + 2) * BKH, NN, tid);
                    }
                    CP_COMMIT();
                }
            }
        }
    }

    // ---- epilogue: h' = relu(1024*(Tbuf @ Wl) + rowsum*bl) ----
    load_tile16(sb + 2 * TILE16, wlt, HID, tid);
    CP_COMMIT();
    __syncthreads();
    load_tile16(sb + 3 * TILE16, wlt + 64, HID, tid);
    CP_COMMIT();

    {
        char* tb = smem + (n_warp >> 6) * TILE16;
        const int lpb = (n_warp & 63) >> 1;
#pragma unroll
        for (int mt = 0; mt < 4; mt++) {
            int mr = m_warp + mt * 16 + g;
#pragma unroll
            for (int nt = 0; nt < 4; nt++) {
                int lp = lpb + nt * 4 + tg;
                int w = lp >> 2, inner = (lp & 3) * 4;
                *reinterpret_cast<uint32_t*>(
                    tb + mr * 128 + (((w ^ (mr & 7))) << 4) + inner) =
                    pack_h2(acc[mt][nt][0] * ST2_F, acc[mt][nt][1] * ST2_F);
                *reinterpret_cast<uint32_t*>(
                    tb + (mr + 8) * 128 + (((w ^ ((mr + 8) & 7))) << 4) + inner) =
                    pack_h2(acc[mt][nt][2] * ST2_F, acc[mt][nt][3] * ST2_F);
            }
        }
    }
    CP_WAIT0();
    __syncthreads();

    float acc2[4][4][4];
#pragma unroll
    for (int mt = 0; mt < 4; mt++)
#pragma unroll
        for (int nt = 0; nt < 4; nt++)
#pragma unroll
            for (int r = 0; r < 4; r++) acc2[mt][nt][r] = 0.f;

#pragma unroll
    for (int ch = 0; ch < 2; ch++) {
        const uint32_t sT = sb + ch * TILE16;
        const uint32_t sW = sb + (2 + ch) * TILE16;
#pragma unroll
        for (int kk = 0; kk < 4; kk++) {
            const uint32_t kx = (uint32_t)kk << 5;
            uint32_t bf2[4][2];
            LDMX4(bf2[0][0], bf2[0][1], bf2[1][0], bf2[1][1], (sW + f.Qb[0]) ^ kx);
            LDMX4(bf2[2][0], bf2[2][1], bf2[3][0], bf2[3][1], (sW + f.Qb[1]) ^ kx);
#pragma unroll
            for (int mt = 0; mt < 4; mt++) {
                uint32_t a0, a1, a2, a3;
                LDMX4(a0, a1, a2, a3, (sT + f.Qa[mt]) ^ kx);
#pragma unroll
                for (int nt = 0; nt < 4; nt++)
                    mma_f16(acc2[mt][nt], a0, a1, a2, a3, bf2[nt][0], bf2[nt][1]);
            }
        }
    }

    float rlo[4], rhi[4];
    if (CONVERT) {
#pragma unroll
        for (int mt = 0; mt < 4; mt++) {
            rlo[mt] = rsm[m_warp + mt * 16 + g];
            rhi[mt] = rsm[m_warp + mt * 16 + g + 8];
        }
    } else {
        const float* rsb = rowsum_in + b * NN + row0;
#pragma unroll
        for (int mt = 0; mt < 4; mt++) {
            rlo[mt] = rsb[m_warp + mt * 16 + g];
            rhi[mt] = rsb[m_warp + mt * 16 + g + 8];
        }
    }
    float b0v[4], b1v[4];
#pragma unroll
    for (int nt = 0; nt < 4; nt++) {
        int col = n_warp + nt * 8 + 2 * tg;
        b0v[nt] = bl[col];
        b1v[nt] = bl[col + 1];
    }

    __half* hb = reinterpret_cast<__half*>(smem + HBUF_OFF);

#pragma unroll
    for (int mt = 0; mt < 4; mt++) {
        int mr = m_warp + mt * 16 + g;
#pragma unroll
        for (int nt = 0; nt < 4; nt++) {
            int col = n_warp + nt * 8 + 2 * tg;
            float v00 = fmaxf(fmaf(acc2[mt][nt][0], UNSC_F, rlo[mt] * b0v[nt]), 0.f);
            float v01 = fmaxf(fmaf(acc2[mt][nt][1], UNSC_F, rlo[mt] * b1v[nt]), 0.f);
            float v10 = fmaxf(fmaf(acc2[mt][nt][2], UNSC_F, rhi[mt] * b0v[nt]), 0.f);
            float v11 = fmaxf(fmaf(acc2[mt][nt][3], UNSC_F, rhi[mt] * b1v[nt]), 0.f);
            if (LAST) {
                *reinterpret_cast<uint32_t*>(
                    &h3out[(size_t)(b * NN + row0 + mr) * HID + col]) =
                    pack_h2(v00 * SP_F, v01 * SP_F);
                *reinterpret_cast<uint32_t*>(
                    &h3out[(size_t)(b * NN + row0 + mr + 8) * HID + col]) =
                    pack_h2(v10 * SP_F, v11 * SP_F);
            } else {
                hb[(col)     * HBUF_STRIDE + mr]     = __float2half(v00 * SH_F);
                hb[(col + 1) * HBUF_STRIDE + mr]     = __float2half(v01 * SH_F);
                hb[(col)     * HBUF_STRIDE + mr + 8] = __float2half(v10 * SH_F);
                hb[(col + 1) * HBUF_STRIDE + mr + 8] = __float2half(v11 * SH_F);
            }
        }
    }

    if (!LAST) {
        __syncthreads();
#pragma unroll
        for (int p = 0; p < 8; p++) {
            int idx = tid + p * 256;
            int c = idx >> 4, u = idx & 15;
            uint4 v = *reinterpret_cast<const uint4*>(hb + c * HBUF_STRIDE + u * 8);
            *reinterpret_cast<uint4*>(
                hTout + ((size_t)(b * HID + c)) * NN + row0 + u * 8) = v;
        }
    }
}

// ============================================================================
// Launch
// Inputs: 0 node_features [B,N,64] | 1 adjacency [B,N,N] | 2 node_mask [B,N,1]
//         3 W_embed [64,128] | 4 Wl [3,128,128] | 5 bl [3,128]
//         6 W_proj [128,64]  | 7 b_proj [64]      Output: [B,N,64] f32
// ============================================================================
extern "C" void kernel_launch(void* const* d_in, const int* in_sizes, int n_in,
                              void* d_out, int out_size)
{
    const float* x     = (const float*)d_in[0];
    const float* adj   = (const float*)d_in[1];
    const float* mask  = (const float*)d_in[2];
    const float* Wemb  = (const float*)d_in[3];
    const float* Wl    = (const float*)d_in[4];
    const float* bl    = (const float*)d_in[5];
    const float* Wproj = (const float*)d_in[6];
    const float* bproj = (const float*)d_in[7];
    float* out = (float*)d_out;

    __half *adjh = nullptr, *hT = nullptr, *wlt = nullptr;
    __half *xh = nullptr, *wembT = nullptr, *wpT = nullptr;
    float *rs = nullptr;
    cudaGetSymbolAddress((void**)&adjh,  g_adjh);
    cudaGetSymbolAddress((void**)&hT,    g_hT);
    cudaGetSymbolAddress((void**)&wlt,   g_WlTh);
    cudaGetSymbolAddress((void**)&xh,    g_xh);
    cudaGetSymbolAddress((void**)&wembT, g_WembTh);
    cudaGetSymbolAddress((void**)&wpT,   g_WprojTh);
    cudaGetSymbolAddress((void**)&rs,    g_rowsum);
    __half* hT0 = hT;
    __half* hT1 = hT + (size_t)BB * HID * NN;
    __half* h3h = hT1;                      // layer-2 input buffer reused for h3

    cudaFuncSetAttribute(adj_layer<false, true>,
                         cudaFuncAttributeMaxDynamicSharedMemorySize, SMTOT);
    cudaFuncSetAttribute(adj_layer<false, false>,
                         cudaFuncAttributeMaxDynamicSharedMemorySize, SMTOT);
    cudaFuncSetAttribute(adj_layer<true, false>,
                         cudaFuncAttributeMaxDynamicSharedMemorySize, SMTOT);
    cudaFuncSetAttribute(embed_mma,
                         cudaFuncAttributeMaxDynamicSharedMemorySize, SMTOT_E);
    cudaFuncSetAttribute(proj_mma,
                         cudaFuncAttributeMaxDynamicSharedMemorySize, SMTOT_P);

    // prep + embed
    prep_weights<<<NUM_LAYERS + 2, 256>>>(Wl, Wemb, Wproj, wlt, wembT, wpT);
    conv_x<<<(BB * NN * IN_DIM) / (4 * 256), 256>>>(x, xh);
    embed_mma<<<BB * NN / 128, 256, SMTOT_E>>>(xh, wembT, hT0);

    dim3 bigg(NN / 128, BB);   // (8, 32)
    // layer 1: reads fp32 adj, writes adjh + rowsum
    adj_layer<false, true><<<bigg, 256, SMTOT>>>(
        adj, adjh, nullptr, hT0, wlt, bl, nullptr, rs, hT1, nullptr);
    // layers 2-3: fp16 adjh path
    adj_layer<false, false><<<bigg, 256, SMTOT>>>(
        nullptr, nullptr, adjh, hT1, wlt + HID * HID, bl + HID, rs, nullptr, hT0, nullptr);
    adj_layer<true, false><<<bigg, 256, SMTOT>>>(
        nullptr, nullptr, adjh, hT0, wlt + 2 * HID * HID, bl + 2 * HID, rs, nullptr,
        nullptr, h3h);

    // projection + mask
    proj_mma<<<BB * NN / 128, 256, SMTOT_P>>>(h3h, wpT, bproj, mask, out);
}

// round 15
// speedup vs baseline: 1.0737x; 1.0737x over previous
#include <cuda_runtime.h>
#include <cuda_fp16.h>
#include <cstdint>

// Problem constants
#define BB 32
#define NN 1024
#define IN_DIM 64
#define HID 128
#define OUTD 64        // 2*LAT
#define NUM_LAYERS 3

// fp16 range management (all powers of two => exact):
//   hT buffers store h * SH (SH=1/16); Tbuf stores T/1024; h3 Tbuf stores h3 * 2^-14
#define SH_F    0.0625f           // 2^-4
#define ST2_F   0.015625f         // 2^-6
#define UNSC_F  1024.0f           // 1/(SH*ST2)
#define SP_F    6.103515625e-05f  // 2^-14
#define UNSC2_F 16384.0f          // 1/SP

// Scratch (device globals; no allocations allowed)
__device__ __half g_adjh[(size_t)BB * NN * NN];       // 67 MB fp16 adjacency
__device__ __half g_hT[2][(size_t)BB * HID * NN];     // ping-pong transposed activations (scaled SH)
__device__ __half g_xh[(size_t)BB * NN * IN_DIM];     // fp16 node features
__device__ float  g_rowsum[BB * NN];                  // per-node adjacency row sums
__device__ __half g_WlTh[NUM_LAYERS * HID * HID];     // Wl transposed, fp16
__device__ __half g_WembTh[HID * IN_DIM];             // Wemb transposed, fp16
__device__ __half g_WprojTh[2 * OUTD * 64];           // WprojT in 2 k-chunks, fp16

// ============================================================================
// Helpers
// ============================================================================
__device__ __forceinline__ uint32_t smem_u32(const void* p) {
    uint32_t a;
    asm("{ .reg .u64 t; cvta.to.shared.u64 t, %1; cvt.u32.u64 %0, t; }"
        : "=r"(a) : "l"(p));
    return a;
}

__device__ __forceinline__ uint32_t pack_h2(float a, float b) {
    __half2 h = __floats2half2_rn(a, b);
    return *reinterpret_cast<uint32_t*>(&h);
}

__device__ __forceinline__ void mma_f16(float c[4],
                                        uint32_t a0, uint32_t a1, uint32_t a2, uint32_t a3,
                                        uint32_t b0, uint32_t b1) {
    asm volatile(
        "mma.sync.aligned.m16n8k16.row.col.f32.f16.f16.f32 "
        "{%0,%1,%2,%3}, {%4,%5,%6,%7}, {%8,%9}, {%0,%1,%2,%3};"
        : "+f"(c[0]), "+f"(c[1]), "+f"(c[2]), "+f"(c[3])
        : "r"(a0), "r"(a1), "r"(a2), "r"(a3), "r"(b0), "r"(b1));
}

#define LDMX4(r0, r1, r2, r3, addr) \
    asm volatile("ldmatrix.sync.aligned.m8n8.x4.shared.b16 {%0,%1,%2,%3}, [%4];" \
                 : "=r"(r0), "=r"(r1), "=r"(r2), "=r"(r3) : "r"(addr))

#define CP_ASYNC16(dst, src) \
    asm volatile("cp.async.cg.shared.global [%0], [%1], 16;" :: "r"(dst), "l"(src))
#define CP_COMMIT() asm volatile("cp.async.commit_group;" ::: "memory")
#define CP_WAIT1()  asm volatile("cp.async.wait_group 1;" ::: "memory")
#define CP_WAIT0()  asm volatile("cp.async.wait_group 0;" ::: "memory")

// Load one 16KB fp16 tile (128 rows x 64 halves, 128B rows) via cp.async.
// 16B word q of row r stored at word q ^ (r&7): conflict-free fill + ldmatrix.
__device__ __forceinline__ void load_tile16(
    uint32_t dst, const __half* __restrict__ src, int rowstride_h, int tid)
{
#pragma unroll
    for (int i = 0; i < 4; i++) {
        int idx = tid + i * 256;             // 0..1023
        int row = idx >> 3;                  // 0..127
        int q   = idx & 7;                   // 16B word
        CP_ASYNC16(dst + row * 128 + ((q ^ (row & 7)) << 4),
                   src + (size_t)row * rowstride_h + q * 8);
    }
}

// 64-row variant (8KB tile)
__device__ __forceinline__ void load_tile8(
    uint32_t dst, const __half* __restrict__ src, int rowstride_h, int tid)
{
#pragma unroll
    for (int i = 0; i < 2; i++) {
        int idx = tid + i * 256;
        int row = idx >> 3;
        int q   = idx & 7;
        CP_ASYNC16(dst + row * 128 + ((q ^ (row & 7)) << 4),
                   src + (size_t)row * rowstride_h + q * 8);
    }
}

// ============================================================================
// Prep: weights transpose+fp16 (blocks 0..4) and x fp32->fp16 (blocks 5..)
// ============================================================================
#define CONVX_BLOCKS ((BB * NN * IN_DIM) / (4 * 256))   // 2048

__global__ __launch_bounds__(256) void prep_all(
    const float* __restrict__ Wl, const float* __restrict__ Wemb,
    const float* __restrict__ Wproj, const float* __restrict__ x,
    __half* __restrict__ wlt, __half* __restrict__ wembT,
    __half* __restrict__ wpT, __half* __restrict__ xh)
{
    int bid = blockIdx.x;
    if (bid < NUM_LAYERS) {
        const float* W = Wl + (size_t)bid * HID * HID;
        __half* T = wlt + (size_t)bid * HID * HID;
        for (int i = threadIdx.x; i < HID * HID; i += blockDim.x) {
            int n2 = i >> 7, n = i & 127;
            T[i] = __float2half(W[n * HID + n2]);
        }
    } else if (bid == NUM_LAYERS) {
        for (int i = threadIdx.x; i < HID * IN_DIM; i += blockDim.x) {
            int o = i >> 6, i2 = i & 63;
            wembT[i] = __float2half(Wemb[i2 * HID + o]);
        }
    } else if (bid == NUM_LAYERS + 1) {
        for (int i = threadIdx.x; i < 2 * OUTD * 64; i += blockDim.x) {
            int c = i >> 12, o = (i >> 6) & 63, f = i & 63;
            wpT[i] = __float2half(Wproj[(64 * c + f) * OUTD + o]);
        }
    } else {
        int idx = (bid - (NUM_LAYERS + 2)) * 256 + threadIdx.x;
        float4 v = *reinterpret_cast<const float4*>(x + (size_t)idx * 4);
        union { __half2 h[2]; uint2 u; } pk;
        pk.h[0] = __floats2half2_rn(v.x, v.y);
        pk.h[1] = __floats2half2_rn(v.z, v.w);
        *reinterpret_cast<uint2*>(xh + (size_t)idx * 4) = pk.u;
    }
}

// adj fp32 -> fp16 copy + per-row sums. One warp per adjacency row.
__global__ __launch_bounds__(256) void conv_rowsum(
    const float* __restrict__ adj, __half* __restrict__ adjh, float* __restrict__ rs)
{
    int warp = (blockIdx.x * blockDim.x + threadIdx.x) >> 5;   // row id
    int lane = threadIdx.x & 31;
    const float* src = adj + (size_t)warp * NN;
    __half* dst = adjh + (size_t)warp * NN;
    float s = 0.f;
#pragma unroll
    for (int i = 0; i < 8; i++) {
        float4 v = *reinterpret_cast<const float4*>(src + i * 128 + lane * 4);
        s += v.x + v.y + v.z + v.w;
        union { __half2 h[2]; uint2 u; } pk;
        pk.h[0] = __floats2half2_rn(v.x, v.y);
        pk.h[1] = __floats2half2_rn(v.z, v.w);
        *reinterpret_cast<uint2*>(dst + i * 128 + lane * 4) = pk.u;
    }
#pragma unroll
    for (int off = 16; off; off >>= 1) s += __shfl_xor_sync(0xFFFFFFFFu, s, off);
    if (lane == 0) rs[warp] = s;
}

// ============================================================================
// Shared fragment-map
// ============================================================================
struct FragMap {
    uint32_t Qa[4];
    uint32_t Qb[2];
    int m_warp, n_warp, g, tg;
};

__device__ __forceinline__ FragMap make_fragmap(int tid, int nwarp_span) {
    FragMap f;
    const int wid = tid >> 5;
    const int lid = tid & 31;
    f.g  = lid >> 2;
    f.tg = lid & 3;
    f.m_warp = (wid & 1) * 64;
    f.n_warp = (wid >> 1) * nwarp_span;
    const int xr  = lid & 7;
    const int rAo = ((lid >> 3) & 1) * 8;
    const int w0A = (lid >> 4) & 1;
#pragma unroll
    for (int mt = 0; mt < 4; mt++) {
        int r = f.m_warp + mt * 16 + rAo + xr;
        f.Qa[mt] = (uint32_t)(r * 128 + ((w0A ^ xr) << 4));
    }
    const int w0B = (lid >> 3) & 1;
    const int ntB = (lid >> 4) & 1;
#pragma unroll
    for (int p = 0; p < 2; p++) {
        int rn = f.n_warp + (p * 2 + ntB) * 8 + xr;
        f.Qb[p] = (uint32_t)(rn * 128 + ((w0B ^ xr) << 4));
    }
    return f;
}

// ============================================================================
// Embed: hT0 = (x @ Wemb)^T * SH
// ============================================================================
#define ETILE 16384
#define HBUF_STRIDE 136
#define EHBUF_OFF (2 * ETILE)
#define SMTOT_E (EHBUF_OFF + 128 * HBUF_STRIDE * 2)    // 67584

__global__ __launch_bounds__(256, 2) void embed_mma(
    const __half* __restrict__ xh, const __half* __restrict__ wembT,
    __half* __restrict__ hTout)
{
    extern __shared__ __align__(1024) char smem[];
    const uint32_t sb = smem_u32(smem);
    const int tid = threadIdx.x;
    const int row0 = blockIdx.x * 128;
    const int b = row0 >> 10;
    const int node0 = row0 & (NN - 1);

    FragMap f = make_fragmap(tid, 32);

    load_tile16(sb,         xh + (size_t)row0 * IN_DIM, IN_DIM, tid);
    load_tile16(sb + ETILE, wembT, IN_DIM, tid);
    CP_COMMIT();

    float acc[4][4][4];
#pragma unroll
    for (int mt = 0; mt < 4; mt++)
#pragma unroll
        for (int nt = 0; nt < 4; nt++)
#pragma unroll
            for (int r = 0; r < 4; r++) acc[mt][nt][r] = 0.f;

    CP_WAIT0();
    __syncthreads();

#pragma unroll
    for (int kk = 0; kk < 4; kk++) {
        const uint32_t kx = (uint32_t)kk << 5;
        uint32_t bf[4][2];
        LDMX4(bf[0][0], bf[0][1], bf[1][0], bf[1][1], (sb + ETILE + f.Qb[0]) ^ kx);
        LDMX4(bf[2][0], bf[2][1], bf[3][0], bf[3][1], (sb + ETILE + f.Qb[1]) ^ kx);
#pragma unroll
        for (int mt = 0; mt < 4; mt++) {
            uint32_t a0, a1, a2, a3;
            LDMX4(a0, a1, a2, a3, (sb + f.Qa[mt]) ^ kx);
#pragma unroll
            for (int nt = 0; nt < 4; nt++)
                mma_f16(acc[mt][nt], a0, a1, a2, a3, bf[nt][0], bf[nt][1]);
        }
    }

    __half* hb = reinterpret_cast<__half*>(smem + EHBUF_OFF);
#pragma unroll
    for (int mt = 0; mt < 4; mt++) {
        int mr = f.m_warp + mt * 16 + f.g;
#pragma unroll
        for (int nt = 0; nt < 4; nt++) {
            int col = f.n_warp + nt * 8 + 2 * f.tg;
            hb[(col)     * HBUF_STRIDE + mr]     = __float2half(acc[mt][nt][0] * SH_F);
            hb[(col + 1) * HBUF_STRIDE + mr]     = __float2half(acc[mt][nt][1] * SH_F);
            hb[(col)     * HBUF_STRIDE + mr + 8] = __float2half(acc[mt][nt][2] * SH_F);
            hb[(col + 1) * HBUF_STRIDE + mr + 8] = __float2half(acc[mt][nt][3] * SH_F);
        }
    }
    __syncthreads();
#pragma unroll
    for (int p = 0; p < 8; p++) {
        int idx = tid + p * 256;
        int c = idx >> 4, u = idx & 15;
        uint4 v = *reinterpret_cast<const uint4*>(hb + c * HBUF_STRIDE + u * 8);
        *reinterpret_cast<uint4*>(
            hTout + ((size_t)(b * HID + c)) * NN + node0 + u * 8) = v;
    }
}

// ============================================================================
// Fused GCN layer (R11 mainloop):
//   acc = adjh @ (h*SH)^T ; Tbuf = acc/64 ; h' = relu(1024*(Tbuf@Wl)+rs*bl)
//   LAST=false: store (h'*SH)^T fp16
//   LAST=true : fused proj — Tbuf2 = h'*2^-14 ; out = (16384*(Tbuf2@Wproj)+bproj)*mask
// ============================================================================
#define ST 3
#define BKH 64
#define NITH (NN / BKH)            // 16
#define TILE16 16384
#define HBUF_OFF (4 * TILE16)
#define SMTOT (HBUF_OFF + 128 * HBUF_STRIDE * 2)   // 100352 B

template<bool LAST>
__global__ __launch_bounds__(256, 2) void adj_layer(
    const __half* __restrict__ adjh, const __half* __restrict__ hTin,
    const __half* __restrict__ wlt,  const float* __restrict__ bl,
    const float* __restrict__ rowsum, __half* __restrict__ hTout,
    const __half* __restrict__ wpT, const float* __restrict__ bproj,
    const float* __restrict__ mask, float* __restrict__ out)
{
    extern __shared__ __align__(1024) char smem[];
    const uint32_t sb = smem_u32(smem);
    const int tid = threadIdx.x;
    const int lid = tid & 31;
    const int b    = blockIdx.y;
    const int row0 = blockIdx.x * 128;

    FragMap f = make_fragmap(tid, 32);
    const int m_warp = f.m_warp, n_warp = f.n_warp, g = f.g, tg = f.tg;

    const __half* Ab = adjh + (size_t)b * NN * NN + (size_t)row0 * NN;
    const __half* Bb = hTin + (size_t)b * HID * NN;

    float acc[4][4][4];
#pragma unroll
    for (int mt = 0; mt < 4; mt++)
#pragma unroll
        for (int nt = 0; nt < 4; nt++)
#pragma unroll
            for (int r = 0; r < 4; r++) acc[mt][nt][r] = 0.f;

    // ---- mainloop (R11 register-pipelined) ----
#pragma unroll
    for (int p = 0; p < 2; p++) {
        load_tile16(sb + p * TILE16, Ab + p * BKH, NN, tid);
        load_tile16(sb + (ST + p) * TILE16, Bb + p * BKH, NN, tid);
        CP_COMMIT();
    }

    for (int it = 0; it < NITH; it++) {
        const int s = it % ST;
        CP_WAIT1();
        __syncthreads();

        const uint32_t sA = sb + s * TILE16;
        const uint32_t sB = sb + (ST + s) * TILE16;

        uint32_t bf[2][4][2];
        uint32_t af[2][4];
        LDMX4(bf[0][0][0], bf[0][0][1], bf[0][1][0], bf[0][1][1], sB + f.Qb[0]);
        LDMX4(bf[0][2][0], bf[0][2][1], bf[0][3][0], bf[0][3][1], sB + f.Qb[1]);
        LDMX4(af[0][0], af[0][1], af[0][2], af[0][3], sA + f.Qa[0]);

#pragma unroll
        for (int kk = 0; kk < 4; kk++) {
            const uint32_t kx  = (uint32_t)kk << 5;
            const uint32_t kxn = (uint32_t)(kk + 1) << 5;
            const int cb = kk & 1, nb = cb ^ 1;
            if (kk < 3) {
                LDMX4(bf[nb][0][0], bf[nb][0][1], bf[nb][1][0], bf[nb][1][1],
                      (sB + f.Qb[0]) ^ kxn);
                LDMX4(bf[nb][2][0], bf[nb][2][1], bf[nb][3][0], bf[nb][3][1],
                      (sB + f.Qb[1]) ^ kxn);
            }
#pragma unroll
            for (int mt = 0; mt < 4; mt++) {
                const int ca = mt & 1, na = ca ^ 1;
                if (mt < 3) {
                    LDMX4(af[na][0], af[na][1], af[na][2], af[na][3],
                          (sA + f.Qa[mt + 1]) ^ kx);
                } else if (kk < 3) {
                    LDMX4(af[na][0], af[na][1], af[na][2], af[na][3],
                          (sA + f.Qa[0]) ^ kxn);
                }
#pragma unroll
                for (int nt = 0; nt < 4; nt++)
                    mma_f16(acc[mt][nt], af[ca][0], af[ca][1], af[ca][2], af[ca][3],
                            bf[cb][nt][0], bf[cb][nt][1]);
            }
            if (kk == 0) {
                if (it + 2 < NITH) {
                    const int sl = (it + 2) % ST;
                    load_tile16(sb + sl * TILE16, Ab + (it + 2) * BKH, NN, tid);
                    load_tile16(sb + (ST + sl) * TILE16, Bb + (it + 2) * BKH, NN, tid);
                }
                CP_COMMIT();
            }
        }
    }

    // ---- epilogue 1: h' = relu(1024*(Tbuf @ Wl) + rowsum*bl) ----
    load_tile16(sb + 2 * TILE16, wlt, HID, tid);
    CP_COMMIT();
    __syncthreads();
    load_tile16(sb + 3 * TILE16, wlt + 64, HID, tid);
    if (LAST) {
        // WprojT chunks into the (unused-in-LAST) hbuf region
        load_tile8(sb + HBUF_OFF,        wpT,             64, tid);
        load_tile8(sb + HBUF_OFF + 8192, wpT + OUTD * 64, 64, tid);
    }
    CP_COMMIT();

    {
        char* tb = smem + (n_warp >> 6) * TILE16;
        const int lpb = (n_warp & 63) >> 1;
#pragma unroll
        for (int mt = 0; mt < 4; mt++) {
            int mr = m_warp + mt * 16 + g;
#pragma unroll
            for (int nt = 0; nt < 4; nt++) {
                int lp = lpb + nt * 4 + tg;
                int w = lp >> 2, inner = (lp & 3) * 4;
                *reinterpret_cast<uint32_t*>(
                    tb + mr * 128 + (((w ^ (mr & 7))) << 4) + inner) =
                    pack_h2(acc[mt][nt][0] * ST2_F, acc[mt][nt][1] * ST2_F);
                *reinterpret_cast<uint32_t*>(
                    tb + (mr + 8) * 128 + (((w ^ ((mr + 8) & 7))) << 4) + inner) =
                    pack_h2(acc[mt][nt][2] * ST2_F, acc[mt][nt][3] * ST2_F);
            }
        }
    }
    CP_WAIT0();
    __syncthreads();

    float acc2[4][4][4];
#pragma unroll
    for (int mt = 0; mt < 4; mt++)
#pragma unroll
        for (int nt = 0; nt < 4; nt++)
#pragma unroll
            for (int r = 0; r < 4; r++) acc2[mt][nt][r] = 0.f;

#pragma unroll
    for (int ch = 0; ch < 2; ch++) {
        const uint32_t sT = sb + ch * TILE16;
        const uint32_t sW = sb + (2 + ch) * TILE16;
#pragma unroll
        for (int kk = 0; kk < 4; kk++) {
            const uint32_t kx = (uint32_t)kk << 5;
            uint32_t bf2[4][2];
            LDMX4(bf2[0][0], bf2[0][1], bf2[1][0], bf2[1][1], (sW + f.Qb[0]) ^ kx);
            LDMX4(bf2[2][0], bf2[2][1], bf2[3][0], bf2[3][1], (sW + f.Qb[1]) ^ kx);
#pragma unroll
            for (int mt = 0; mt < 4; mt++) {
                uint32_t a0, a1, a2, a3;
                LDMX4(a0, a1, a2, a3, (sT + f.Qa[mt]) ^ kx);
#pragma unroll
                for (int nt = 0; nt < 4; nt++)
                    mma_f16(acc2[mt][nt], a0, a1, a2, a3, bf2[nt][0], bf2[nt][1]);
            }
        }
    }

    const float* rsb = rowsum + b * NN + row0;
    float rlo[4], rhi[4];
#pragma unroll
    for (int mt = 0; mt < 4; mt++) {
        rlo[mt] = rsb[m_warp + mt * 16 + g];
        rhi[mt] = rsb[m_warp + mt * 16 + g + 8];
    }
    float b0v[4], b1v[4];
#pragma unroll
    for (int nt = 0; nt < 4; nt++) {
        int col = n_warp + nt * 8 + 2 * tg;
        b0v[nt] = bl[col];
        b1v[nt] = bl[col + 1];
    }

    __half* hb = reinterpret_cast<__half*>(smem + HBUF_OFF);

    if (LAST) __syncthreads();     // all warps done reading Tbuf/Wl before overwrite

#pragma unroll
    for (int mt = 0; mt < 4; mt++) {
        int mr = m_warp + mt * 16 + g;
#pragma unroll
        for (int nt = 0; nt < 4; nt++) {
            int col = n_warp + nt * 8 + 2 * tg;
            float v00 = fmaxf(fmaf(acc2[mt][nt][0], UNSC_F, rlo[mt] * b0v[nt]), 0.f);
            float v01 = fmaxf(fmaf(acc2[mt][nt][1], UNSC_F, rlo[mt] * b1v[nt]), 0.f);
            float v10 = fmaxf(fmaf(acc2[mt][nt][2], UNSC_F, rhi[mt] * b0v[nt]), 0.f);
            float v11 = fmaxf(fmaf(acc2[mt][nt][3], UNSC_F, rhi[mt] * b1v[nt]), 0.f);
            if (LAST) {
                // Tbuf2 = h3 * 2^-14 back into slots 0/1 (same proven pattern)
                char* tb = smem + (n_warp >> 6) * TILE16;
                const int lpb = (n_warp & 63) >> 1;
                int lp = lpb + nt * 4 + tg;
                int w = lp >> 2, inner = (lp & 3) * 4;
                *reinterpret_cast<uint32_t*>(
                    tb + mr * 128 + (((w ^ (mr & 7))) << 4) + inner) =
                    pack_h2(v00 * SP_F, v01 * SP_F);
                *reinterpret_cast<uint32_t*>(
                    tb + (mr + 8) * 128 + (((w ^ ((mr + 8) & 7))) << 4) + inner) =
                    pack_h2(v10 * SP_F, v11 * SP_F);
            } else {
                hb[(col)     * HBUF_STRIDE + mr]     = __float2half(v00 * SH_F);
                hb[(col + 1) * HBUF_STRIDE + mr]     = __float2half(v01 * SH_F);
                hb[(col)     * HBUF_STRIDE + mr + 8] = __float2half(v10 * SH_F);
                hb[(col + 1) * HBUF_STRIDE + mr + 8] = __float2half(v11 * SH_F);
            }
        }
    }

    if (!LAST) {
        __syncthreads();
        // coalesced h'T store: feat row c -> hTout[b][c][row0 .. row0+127]
#pragma unroll
        for (int p = 0; p < 8; p++) {
            int idx = tid + p * 256;
            int c = idx >> 4, u = idx & 15;
            uint4 v = *reinterpret_cast<const uint4*>(hb + c * HBUF_STRIDE + u * 8);
            *reinterpret_cast<uint4*>(
                hTout + ((size_t)(b * HID + c)) * NN + row0 + u * 8) = v;
        }
    } else {
        // ---- epilogue 2 (fused proj): out = (16384*(Tbuf2 @ Wproj) + bproj)*mask ----
        __syncthreads();           // Tbuf2 fully written

        // span-16 B fragment address (N=64 over 8 warps -> 16 cols/warp, 1 LDSM.x4)
        const int n_warp2 = ((tid >> 5) >> 1) * 16;
        const int xr  = lid & 7;
        const int w0B = (lid >> 3) & 1;
        const int ntB = (lid >> 4) & 1;
        const uint32_t Qb2 = (uint32_t)((n_warp2 + ntB * 8 + xr) * 128 + ((w0B ^ xr) << 4));

        float acc3[4][2][4];
#pragma unroll
        for (int mt = 0; mt < 4; mt++)
#pragma unroll
            for (int nt = 0; nt < 2; nt++)
#pragma unroll
                for (int r = 0; r < 4; r++) acc3[mt][nt][r] = 0.f;

#pragma unroll
        for (int ch = 0; ch < 2; ch++) {
            const uint32_t sT = sb + ch * TILE16;
            const uint32_t sW = sb + HBUF_OFF + ch * 8192;
#pragma unroll
            for (int kk = 0; kk < 4; kk++) {
                const uint32_t kx = (uint32_t)kk << 5;
                uint32_t bf3[2][2];
                LDMX4(bf3[0][0], bf3[0][1], bf3[1][0], bf3[1][1], (sW + Qb2) ^ kx);
#pragma unroll
                for (int mt = 0; mt < 4; mt++) {
                    uint32_t a0, a1, a2, a3;
                    LDMX4(a0, a1, a2, a3, (sT + f.Qa[mt]) ^ kx);
#pragma unroll
                    for (int nt = 0; nt < 2; nt++)
                        mma_f16(acc3[mt][nt], a0, a1, a2, a3, bf3[nt][0], bf3[nt][1]);
                }
            }
        }

#pragma unroll
        for (int mt = 0; mt < 4; mt++) {
            int grow = b * NN + row0 + m_warp + mt * 16 + g;
            float m0 = mask[grow], m1 = mask[grow + 8];
#pragma unroll
            for (int nt = 0; nt < 2; nt++) {
                int col = n_warp2 + nt * 8 + 2 * tg;
                float pb0 = bproj[col], pb1 = bproj[col + 1];
                float2 p0, p1;
                p0.x = fmaf(acc3[mt][nt][0], UNSC2_F, pb0) * m0;
                p0.y = fmaf(acc3[mt][nt][1], UNSC2_F, pb1) * m0;
                p1.x = fmaf(acc3[mt][nt][2], UNSC2_F, pb0) * m1;
                p1.y = fmaf(acc3[mt][nt][3], UNSC2_F, pb1) * m1;
                *reinterpret_cast<float2*>(&out[(size_t)grow * OUTD + col])       = p0;
                *reinterpret_cast<float2*>(&out[(size_t)(grow + 8) * OUTD + col]) = p1;
            }
        }
    }
}

// ============================================================================
// Launch
// Inputs: 0 node_features [B,N,64] | 1 adjacency [B,N,N] | 2 node_mask [B,N,1]
//         3 W_embed [64,128] | 4 Wl [3,128,128] | 5 bl [3,128]
//         6 W_proj [128,64]  | 7 b_proj [64]      Output: [B,N,64] f32
// ============================================================================
extern "C" void kernel_launch(void* const* d_in, const int* in_sizes, int n_in,
                              void* d_out, int out_size)
{
    const float* x     = (const float*)d_in[0];
    const float* adj   = (const float*)d_in[1];
    const float* mask  = (const float*)d_in[2];
    const float* Wemb  = (const float*)d_in[3];
    const float* Wl    = (const float*)d_in[4];
    const float* bl    = (const float*)d_in[5];
    const float* Wproj = (const float*)d_in[6];
    const float* bproj = (const float*)d_in[7];
    float* out = (float*)d_out;

    __half *adjh = nullptr, *hT = nullptr, *wlt = nullptr;
    __half *xh = nullptr, *wembT = nullptr, *wpT = nullptr;
    float *rs = nullptr;
    cudaGetSymbolAddress((void**)&adjh,  g_adjh);
    cudaGetSymbolAddress((void**)&hT,    g_hT);
    cudaGetSymbolAddress((void**)&wlt,   g_WlTh);
    cudaGetSymbolAddress((void**)&xh,    g_xh);
    cudaGetSymbolAddress((void**)&wembT, g_WembTh);
    cudaGetSymbolAddress((void**)&wpT,   g_WprojTh);
    cudaGetSymbolAddress((void**)&rs,    g_rowsum);
    __half* hT0 = hT;
    __half* hT1 = hT + (size_t)BB * HID * NN;

    cudaFuncSetAttribute(adj_layer<false>,
                         cudaFuncAttributeMaxDynamicSharedMemorySize, SMTOT);
    cudaFuncSetAttribute(adj_layer<true>,
                         cudaFuncAttributeMaxDynamicSharedMemorySize, SMTOT);
    cudaFuncSetAttribute(embed_mma,
                         cudaFuncAttributeMaxDynamicSharedMemorySize, SMTOT_E);

    // prep (weights + x conversion fused) -> embed ; adj conversion + rowsums
    prep_all<<<NUM_LAYERS + 2 + CONVX_BLOCKS, 256>>>(
        Wl, Wemb, Wproj, x, wlt, wembT, wpT, xh);
    embed_mma<<<BB * NN / 128, 256, SMTOT_E>>>(xh, wembT, hT0);
    conv_rowsum<<<BB * NN / 8, 256>>>(adj, adjh, rs);

    dim3 bigg(NN / 128, BB);   // (8, 32)
    adj_layer<false><<<bigg, 256, SMTOT>>>(
        adjh, hT0, wlt,                 bl,           rs, hT1,
        nullptr, nullptr, nullptr, nullptr);
    adj_layer<false><<<bigg, 256, SMTOT>>>(
        adjh, hT1, wlt + HID * HID,     bl + HID,     rs, hT0,
        nullptr, nullptr, nullptr, nullptr);
    adj_layer<true><<<bigg, 256, SMTOT>>>(
        adjh, hT0, wlt + 2 * HID * HID, bl + 2 * HID, rs, nullptr,
        wpT, bproj, mask, out);
}

// round 16
// speedup vs baseline: 1.0856x; 1.0111x over previous
#include <cuda_runtime.h>
#include <cuda_fp16.h>
#include <cstdint>

// Problem constants
#define BB 32
#define NN 1024
#define IN_DIM 64
#define HID 128
#define OUTD 64        // 2*LAT
#define NUM_LAYERS 3

// fp16 range management (all powers of two => exact):
//   hT buffers store h * SH (SH=1/16); Tbuf stores T/1024; h3 Tbuf stores h3 * 2^-14
#define SH_F    0.0625f           // 2^-4
#define ST2_F   0.015625f         // 2^-6
#define UNSC_F  1024.0f           // 1/(SH*ST2)
#define SP_F    6.103515625e-05f  // 2^-14
#define UNSC2_F 16384.0f          // 1/SP

// Scratch (device globals; no allocations allowed)
__device__ __half g_adjh[(size_t)BB * NN * NN];       // 67 MB fp16 adjacency
__device__ __half g_hT[2][(size_t)BB * HID * NN];     // ping-pong transposed activations (scaled SH)
__device__ __half g_xh[(size_t)BB * NN * IN_DIM];     // fp16 node features
__device__ float  g_rowsum[BB * NN];                  // per-node adjacency row sums
__device__ __half g_WlTh[NUM_LAYERS * HID * HID];     // Wl transposed, fp16
__device__ __half g_WembTh[HID * IN_DIM];             // Wemb transposed, fp16
__device__ __half g_WprojTh[2 * OUTD * 64];           // WprojT in 2 k-chunks, fp16

// ============================================================================
// Helpers
// ============================================================================
__device__ __forceinline__ uint32_t smem_u32(const void* p) {
    uint32_t a;
    asm("{ .reg .u64 t; cvta.to.shared.u64 t, %1; cvt.u32.u64 %0, t; }"
        : "=r"(a) : "l"(p));
    return a;
}

__device__ __forceinline__ uint32_t pack_h2(float a, float b) {
    __half2 h = __floats2half2_rn(a, b);
    return *reinterpret_cast<uint32_t*>(&h);
}

__device__ __forceinline__ void mma_f16(float c[4],
                                        uint32_t a0, uint32_t a1, uint32_t a2, uint32_t a3,
                                        uint32_t b0, uint32_t b1) {
    asm volatile(
        "mma.sync.aligned.m16n8k16.row.col.f32.f16.f16.f32 "
        "{%0,%1,%2,%3}, {%4,%5,%6,%7}, {%8,%9}, {%0,%1,%2,%3};"
        : "+f"(c[0]), "+f"(c[1]), "+f"(c[2]), "+f"(c[3])
        : "r"(a0), "r"(a1), "r"(a2), "r"(a3), "r"(b0), "r"(b1));
}

#define LDMX4(r0, r1, r2, r3, addr) \
    asm volatile("ldmatrix.sync.aligned.m8n8.x4.shared.b16 {%0,%1,%2,%3}, [%4];" \
                 : "=r"(r0), "=r"(r1), "=r"(r2), "=r"(r3) : "r"(addr))

#define CP_ASYNC16(dst, src) \
    asm volatile("cp.async.cg.shared.global [%0], [%1], 16;" :: "r"(dst), "l"(src))
#define CP_COMMIT() asm volatile("cp.async.commit_group;" ::: "memory")
#define CP_WAIT1()  asm volatile("cp.async.wait_group 1;" ::: "memory")
#define CP_WAIT0()  asm volatile("cp.async.wait_group 0;" ::: "memory")

// Load one 16KB fp16 tile (128 rows x 64 halves, 128B rows) via cp.async.
// 16B word q of row r stored at word q ^ (r&7): conflict-free fill + ldmatrix.
__device__ __forceinline__ void load_tile16(
    uint32_t dst, const __half* __restrict__ src, int rowstride_h, int tid)
{
#pragma unroll
    for (int i = 0; i < 4; i++) {
        int idx = tid + i * 256;             // 0..1023
        int row = idx >> 3;                  // 0..127
        int q   = idx & 7;                   // 16B word
        CP_ASYNC16(dst + row * 128 + ((q ^ (row & 7)) << 4),
                   src + (size_t)row * rowstride_h + q * 8);
    }
}

// 64-row variant (8KB tile)
__device__ __forceinline__ void load_tile8(
    uint32_t dst, const __half* __restrict__ src, int rowstride_h, int tid)
{
#pragma unroll
    for (int i = 0; i < 2; i++) {
        int idx = tid + i * 256;
        int row = idx >> 3;
        int q   = idx & 7;
        CP_ASYNC16(dst + row * 128 + ((q ^ (row & 7)) << 4),
                   src + (size_t)row * rowstride_h + q * 8);
    }
}

// ============================================================================
// Prep: weights transpose+fp16 (blocks 0..4) and x fp32->fp16 (blocks 5..)
// ============================================================================
#define CONVX_BLOCKS ((BB * NN * IN_DIM) / (4 * 256))   // 2048

__global__ __launch_bounds__(256) void prep_all(
    const float* __restrict__ Wl, const float* __restrict__ Wemb,
    const float* __restrict__ Wproj, const float* __restrict__ x,
    __half* __restrict__ wlt, __half* __restrict__ wembT,
    __half* __restrict__ wpT, __half* __restrict__ xh)
{
    int bid = blockIdx.x;
    if (bid < NUM_LAYERS) {
        const float* W = Wl + (size_t)bid * HID * HID;
        __half* T = wlt + (size_t)bid * HID * HID;
        for (int i = threadIdx.x; i < HID * HID; i += blockDim.x) {
            int n2 = i >> 7, n = i & 127;
            T[i] = __float2half(W[n * HID + n2]);
        }
    } else if (bid == NUM_LAYERS) {
        for (int i = threadIdx.x; i < HID * IN_DIM; i += blockDim.x) {
            int o = i >> 6, i2 = i & 63;
            wembT[i] = __float2half(Wemb[i2 * HID + o]);
        }
    } else if (bid == NUM_LAYERS + 1) {
        for (int i = threadIdx.x; i < 2 * OUTD * 64; i += blockDim.x) {
            int c = i >> 12, o = (i >> 6) & 63, f = i & 63;
            wpT[i] = __float2half(Wproj[(64 * c + f) * OUTD + o]);
        }
    } else {
        int idx = (bid - (NUM_LAYERS + 2)) * 256 + threadIdx.x;
        float4 v = *reinterpret_cast<const float4*>(x + (size_t)idx * 4);
        union { __half2 h[2]; uint2 u; } pk;
        pk.h[0] = __floats2half2_rn(v.x, v.y);
        pk.h[1] = __floats2half2_rn(v.z, v.w);
        *reinterpret_cast<uint2*>(xh + (size_t)idx * 4) = pk.u;
    }
}

// adj fp32 -> fp16 copy + per-row sums. One warp per adjacency row.
__global__ __launch_bounds__(256) void conv_rowsum(
    const float* __restrict__ adj, __half* __restrict__ adjh, float* __restrict__ rs)
{
    int warp = (blockIdx.x * blockDim.x + threadIdx.x) >> 5;   // row id
    int lane = threadIdx.x & 31;
    const float* src = adj + (size_t)warp * NN;
    __half* dst = adjh + (size_t)warp * NN;
    float s = 0.f;
#pragma unroll
    for (int i = 0; i < 8; i++) {
        float4 v = *reinterpret_cast<const float4*>(src + i * 128 + lane * 4);
        s += v.x + v.y + v.z + v.w;
        union { __half2 h[2]; uint2 u; } pk;
        pk.h[0] = __floats2half2_rn(v.x, v.y);
        pk.h[1] = __floats2half2_rn(v.z, v.w);
        *reinterpret_cast<uint2*>(dst + i * 128 + lane * 4) = pk.u;
    }
#pragma unroll
    for (int off = 16; off; off >>= 1) s += __shfl_xor_sync(0xFFFFFFFFu, s, off);
    if (lane == 0) rs[warp] = s;
}

// ============================================================================
// Shared fragment-map
// ============================================================================
struct FragMap {
    uint32_t Qa[4];
    uint32_t Qb[2];
    int m_warp, n_warp, g, tg;
};

__device__ __forceinline__ FragMap make_fragmap(int tid, int nwarp_span) {
    FragMap f;
    const int wid = tid >> 5;
    const int lid = tid & 31;
    f.g  = lid >> 2;
    f.tg = lid & 3;
    f.m_warp = (wid & 1) * 64;
    f.n_warp = (wid >> 1) * nwarp_span;
    const int xr  = lid & 7;
    const int rAo = ((lid >> 3) & 1) * 8;
    const int w0A = (lid >> 4) & 1;
#pragma unroll
    for (int mt = 0; mt < 4; mt++) {
        int r = f.m_warp + mt * 16 + rAo + xr;
        f.Qa[mt] = (uint32_t)(r * 128 + ((w0A ^ xr) << 4));
    }
    const int w0B = (lid >> 3) & 1;
    const int ntB = (lid >> 4) & 1;
#pragma unroll
    for (int p = 0; p < 2; p++) {
        int rn = f.n_warp + (p * 2 + ntB) * 8 + xr;
        f.Qb[p] = (uint32_t)(rn * 128 + ((w0B ^ xr) << 4));
    }
    return f;
}

// ============================================================================
// Embed: hT0 = (x @ Wemb)^T * SH
// ============================================================================
#define ETILE 16384
#define HBUF_STRIDE 136
#define EHBUF_OFF (2 * ETILE)
#define SMTOT_E (EHBUF_OFF + 128 * HBUF_STRIDE * 2)    // 67584

__global__ __launch_bounds__(256, 2) void embed_mma(
    const __half* __restrict__ xh, const __half* __restrict__ wembT,
    __half* __restrict__ hTout)
{
    extern __shared__ __align__(1024) char smem[];
    const uint32_t sb = smem_u32(smem);
    const int tid = threadIdx.x;
    const int row0 = blockIdx.x * 128;
    const int b = row0 >> 10;
    const int node0 = row0 & (NN - 1);

    FragMap f = make_fragmap(tid, 32);

    load_tile16(sb,         xh + (size_t)row0 * IN_DIM, IN_DIM, tid);
    load_tile16(sb + ETILE, wembT, IN_DIM, tid);
    CP_COMMIT();

    float acc[4][4][4];
#pragma unroll
    for (int mt = 0; mt < 4; mt++)
#pragma unroll
        for (int nt = 0; nt < 4; nt++)
#pragma unroll
            for (int r = 0; r < 4; r++) acc[mt][nt][r] = 0.f;

    CP_WAIT0();
    __syncthreads();

#pragma unroll
    for (int kk = 0; kk < 4; kk++) {
        const uint32_t kx = (uint32_t)kk << 5;
        uint32_t bf[4][2];
        LDMX4(bf[0][0], bf[0][1], bf[1][0], bf[1][1], (sb + ETILE + f.Qb[0]) ^ kx);
        LDMX4(bf[2][0], bf[2][1], bf[3][0], bf[3][1], (sb + ETILE + f.Qb[1]) ^ kx);
#pragma unroll
        for (int mt = 0; mt < 4; mt++) {
            uint32_t a0, a1, a2, a3;
            LDMX4(a0, a1, a2, a3, (sb + f.Qa[mt]) ^ kx);
#pragma unroll
            for (int nt = 0; nt < 4; nt++)
                mma_f16(acc[mt][nt], a0, a1, a2, a3, bf[nt][0], bf[nt][1]);
        }
    }

    __half* hb = reinterpret_cast<__half*>(smem + EHBUF_OFF);
#pragma unroll
    for (int mt = 0; mt < 4; mt++) {
        int mr = f.m_warp + mt * 16 + f.g;
#pragma unroll
        for (int nt = 0; nt < 4; nt++) {
            int col = f.n_warp + nt * 8 + 2 * f.tg;
            hb[(col)     * HBUF_STRIDE + mr]     = __float2half(acc[mt][nt][0] * SH_F);
            hb[(col + 1) * HBUF_STRIDE + mr]     = __float2half(acc[mt][nt][1] * SH_F);
            hb[(col)     * HBUF_STRIDE + mr + 8] = __float2half(acc[mt][nt][2] * SH_F);
            hb[(col + 1) * HBUF_STRIDE + mr + 8] = __float2half(acc[mt][nt][3] * SH_F);
        }
    }
    __syncthreads();
#pragma unroll
    for (int p = 0; p < 8; p++) {
        int idx = tid + p * 256;
        int c = idx >> 4, u = idx & 15;
        uint4 v = *reinterpret_cast<const uint4*>(hb + c * HBUF_STRIDE + u * 8);
        *reinterpret_cast<uint4*>(
            hTout + ((size_t)(b * HID + c)) * NN + node0 + u * 8) = v;
    }
}

// ============================================================================
// Fused GCN layer (R11 mainloop):
//   acc = adjh @ (h*SH)^T ; Tbuf = acc/64 ; h' = relu(1024*(Tbuf@Wl)+rs*bl)
//   LAST=false: store (h'*SH)^T fp16
//   LAST=true : fused proj — Tbuf2 = h'*2^-14 ; out = (16384*(Tbuf2@Wproj)+bproj)*mask
// ============================================================================
#define ST 3
#define BKH 64
#define NITH (NN / BKH)            // 16
#define TILE16 16384
#define HBUF_OFF (4 * TILE16)
#define SMTOT (HBUF_OFF + 128 * HBUF_STRIDE * 2)   // 100352 B

template<bool LAST>
__global__ __launch_bounds__(256, 2) void adj_layer(
    const __half* __restrict__ adjh, const __half* __restrict__ hTin,
    const __half* __restrict__ wlt,  const float* __restrict__ bl,
    const float* __restrict__ rowsum, __half* __restrict__ hTout,
    const __half* __restrict__ wpT, const float* __restrict__ bproj,
    const float* __restrict__ mask, float* __restrict__ out)
{
    extern __shared__ __align__(1024) char smem[];
    const uint32_t sb = smem_u32(smem);
    const int tid = threadIdx.x;
    const int lid = tid & 31;
    const int b    = blockIdx.y;
    const int row0 = blockIdx.x * 128;

    FragMap f = make_fragmap(tid, 32);
    const int m_warp = f.m_warp, n_warp = f.n_warp, g = f.g, tg = f.tg;

    const __half* Ab = adjh + (size_t)b * NN * NN + (size_t)row0 * NN;
    const __half* Bb = hTin + (size_t)b * HID * NN;

    float acc[4][4][4];
#pragma unroll
    for (int mt = 0; mt < 4; mt++)
#pragma unroll
        for (int nt = 0; nt < 4; nt++)
#pragma unroll
            for (int r = 0; r < 4; r++) acc[mt][nt][r] = 0.f;

    // ---- mainloop (R11 register-pipelined) ----
#pragma unroll
    for (int p = 0; p < 2; p++) {
        load_tile16(sb + p * TILE16, Ab + p * BKH, NN, tid);
        load_tile16(sb + (ST + p) * TILE16, Bb + p * BKH, NN, tid);
        CP_COMMIT();
    }

    for (int it = 0; it < NITH; it++) {
        const int s = it % ST;
        CP_WAIT1();
        __syncthreads();

        const uint32_t sA = sb + s * TILE16;
        const uint32_t sB = sb + (ST + s) * TILE16;

        uint32_t bf[2][4][2];
        uint32_t af[2][4];
        LDMX4(bf[0][0][0], bf[0][0][1], bf[0][1][0], bf[0][1][1], sB + f.Qb[0]);
        LDMX4(bf[0][2][0], bf[0][2][1], bf[0][3][0], bf[0][3][1], sB + f.Qb[1]);
        LDMX4(af[0][0], af[0][1], af[0][2], af[0][3], sA + f.Qa[0]);

#pragma unroll
        for (int kk = 0; kk < 4; kk++) {
            const uint32_t kx  = (uint32_t)kk << 5;
            const uint32_t kxn = (uint32_t)(kk + 1) << 5;
            const int cb = kk & 1, nb = cb ^ 1;
            if (kk < 3) {
                LDMX4(bf[nb][0][0], bf[nb][0][1], bf[nb][1][0], bf[nb][1][1],
                      (sB + f.Qb[0]) ^ kxn);
                LDMX4(bf[nb][2][0], bf[nb][2][1], bf[nb][3][0], bf[nb][3][1],
                      (sB + f.Qb[1]) ^ kxn);
            }
#pragma unroll
            for (int mt = 0; mt < 4; mt++) {
                const int ca = mt & 1, na = ca ^ 1;
                if (mt < 3) {
                    LDMX4(af[na][0], af[na][1], af[na][2], af[na][3],
                          (sA + f.Qa[mt + 1]) ^ kx);
                } else if (kk < 3) {
                    LDMX4(af[na][0], af[na][1], af[na][2], af[na][3],
                          (sA + f.Qa[0]) ^ kxn);
                }
#pragma unroll
                for (int nt = 0; nt < 4; nt++)
                    mma_f16(acc[mt][nt], af[ca][0], af[ca][1], af[ca][2], af[ca][3],
                            bf[cb][nt][0], bf[cb][nt][1]);
            }
            if (kk == 0) {
                if (it + 2 < NITH) {
                    const int sl = (it + 2) % ST;
                    load_tile16(sb + sl * TILE16, Ab + (it + 2) * BKH, NN, tid);
                    load_tile16(sb + (ST + sl) * TILE16, Bb + (it + 2) * BKH, NN, tid);
                }
                CP_COMMIT();
            }
        }
    }

    // ---- epilogue 1: h' = relu(1024*(Tbuf @ Wl) + rowsum*bl) ----
    load_tile16(sb + 2 * TILE16, wlt, HID, tid);
    CP_COMMIT();
    __syncthreads();
    load_tile16(sb + 3 * TILE16, wlt + 64, HID, tid);
    if (LAST) {
        // WprojT chunks into the (unused-in-LAST) hbuf region
        load_tile8(sb + HBUF_OFF,        wpT,             64, tid);
        load_tile8(sb + HBUF_OFF + 8192, wpT + OUTD * 64, 64, tid);
    }
    CP_COMMIT();

    {
        char* tb = smem + (n_warp >> 6) * TILE16;
        const int lpb = (n_warp & 63) >> 1;
#pragma unroll
        for (int mt = 0; mt < 4; mt++) {
            int mr = m_warp + mt * 16 + g;
#pragma unroll
            for (int nt = 0; nt < 4; nt++) {
                int lp = lpb + nt * 4 + tg;
                int w = lp >> 2, inner = (lp & 3) * 4;
                *reinterpret_cast<uint32_t*>(
                    tb + mr * 128 + (((w ^ (mr & 7))) << 4) + inner) =
                    pack_h2(acc[mt][nt][0] * ST2_F, acc[mt][nt][1] * ST2_F);
                *reinterpret_cast<uint32_t*>(
                    tb + (mr + 8) * 128 + (((w ^ ((mr + 8) & 7))) << 4) + inner) =
                    pack_h2(acc[mt][nt][2] * ST2_F, acc[mt][nt][3] * ST2_F);
            }
        }
    }
    CP_WAIT0();
    __syncthreads();

    float acc2[4][4][4];
#pragma unroll
    for (int mt = 0; mt < 4; mt++)
#pragma unroll
        for (int nt = 0; nt < 4; nt++)
#pragma unroll
            for (int r = 0; r < 4; r++) acc2[mt][nt][r] = 0.f;

#pragma unroll
    for (int ch = 0; ch < 2; ch++) {
        const uint32_t sT = sb + ch * TILE16;
        const uint32_t sW = sb + (2 + ch) * TILE16;
#pragma unroll
        for (int kk = 0; kk < 4; kk++) {
            const uint32_t kx = (uint32_t)kk << 5;
            uint32_t bf2[4][2];
            LDMX4(bf2[0][0], bf2[0][1], bf2[1][0], bf2[1][1], (sW + f.Qb[0]) ^ kx);
            LDMX4(bf2[2][0], bf2[2][1], bf2[3][0], bf2[3][1], (sW + f.Qb[1]) ^ kx);
#pragma unroll
            for (int mt = 0; mt < 4; mt++) {
                uint32_t a0, a1, a2, a3;
                LDMX4(a0, a1, a2, a3, (sT + f.Qa[mt]) ^ kx);
#pragma unroll
                for (int nt = 0; nt < 4; nt++)
                    mma_f16(acc2[mt][nt], a0, a1, a2, a3, bf2[nt][0], bf2[nt][1]);
            }
        }
    }

    const float* rsb = rowsum + b * NN + row0;
    float rlo[4], rhi[4];
#pragma unroll
    for (int mt = 0; mt < 4; mt++) {
        rlo[mt] = rsb[m_warp + mt * 16 + g];
        rhi[mt] = rsb[m_warp + mt * 16 + g + 8];
    }
    float b0v[4], b1v[4];
#pragma unroll
    for (int nt = 0; nt < 4; nt++) {
        int col = n_warp + nt * 8 + 2 * tg;
        b0v[nt] = bl[col];
        b1v[nt] = bl[col + 1];
    }

    __half* hb = reinterpret_cast<__half*>(smem + HBUF_OFF);

    if (LAST) __syncthreads();     // all warps done reading Tbuf/Wl before overwrite

#pragma unroll
    for (int mt = 0; mt < 4; mt++) {
        int mr = m_warp + mt * 16 + g;
#pragma unroll
        for (int nt = 0; nt < 4; nt++) {
            int col = n_warp + nt * 8 + 2 * tg;
            float v00 = fmaxf(fmaf(acc2[mt][nt][0], UNSC_F, rlo[mt] * b0v[nt]), 0.f);
            float v01 = fmaxf(fmaf(acc2[mt][nt][1], UNSC_F, rlo[mt] * b1v[nt]), 0.f);
            float v10 = fmaxf(fmaf(acc2[mt][nt][2], UNSC_F, rhi[mt] * b0v[nt]), 0.f);
            float v11 = fmaxf(fmaf(acc2[mt][nt][3], UNSC_F, rhi[mt] * b1v[nt]), 0.f);
            if (LAST) {
                // Tbuf2 = h3 * 2^-14 back into slots 0/1 (same proven pattern)
                char* tb = smem + (n_warp >> 6) * TILE16;
                const int lpb = (n_warp & 63) >> 1;
                int lp = lpb + nt * 4 + tg;
                int w = lp >> 2, inner = (lp & 3) * 4;
                *reinterpret_cast<uint32_t*>(
                    tb + mr * 128 + (((w ^ (mr & 7))) << 4) + inner) =
                    pack_h2(v00 * SP_F, v01 * SP_F);
                *reinterpret_cast<uint32_t*>(
                    tb + (mr + 8) * 128 + (((w ^ ((mr + 8) & 7))) << 4) + inner) =
                    pack_h2(v10 * SP_F, v11 * SP_F);
            } else {
                hb[(col)     * HBUF_STRIDE + mr]     = __float2half(v00 * SH_F);
                hb[(col + 1) * HBUF_STRIDE + mr]     = __float2half(v01 * SH_F);
                hb[(col)     * HBUF_STRIDE + mr + 8] = __float2half(v10 * SH_F);
                hb[(col + 1) * HBUF_STRIDE + mr + 8] = __float2half(v11 * SH_F);
            }
        }
    }

    if (!LAST) {
        __syncthreads();
        // coalesced h'T store: feat row c -> hTout[b][c][row0 .. row0+127]
#pragma unroll
        for (int p = 0; p < 8; p++) {
            int idx = tid + p * 256;
            int c = idx >> 4, u = idx & 15;
            uint4 v = *reinterpret_cast<const uint4*>(hb + c * HBUF_STRIDE + u * 8);
            *reinterpret_cast<uint4*>(
                hTout + ((size_t)(b * HID + c)) * NN + row0 + u * 8) = v;
        }
    } else {
        // ---- epilogue 2 (fused proj): out = (16384*(Tbuf2 @ Wproj) + bproj)*mask ----
        __syncthreads();           // Tbuf2 fully written

        // span-16 B fragment address (N=64 over 8 warps -> 16 cols/warp, 1 LDSM.x4)
        const int n_warp2 = ((tid >> 5) >> 1) * 16;
        const int xr  = lid & 7;
        const int w0B = (lid >> 3) & 1;
        const int ntB = (lid >> 4) & 1;
        const uint32_t Qb2 = (uint32_t)((n_warp2 + ntB * 8 + xr) * 128 + ((w0B ^ xr) << 4));

        float acc3[4][2][4];
#pragma unroll
        for (int mt = 0; mt < 4; mt++)
#pragma unroll
            for (int nt = 0; nt < 2; nt++)
#pragma unroll
                for (int r = 0; r < 4; r++) acc3[mt][nt][r] = 0.f;

#pragma unroll
        for (int ch = 0; ch < 2; ch++) {
            const uint32_t sT = sb + ch * TILE16;
            const uint32_t sW = sb + HBUF_OFF + ch * 8192;
#pragma unroll
            for (int kk = 0; kk < 4; kk++) {
                const uint32_t kx = (uint32_t)kk << 5;
                uint32_t bf3[2][2];
                LDMX4(bf3[0][0], bf3[0][1], bf3[1][0], bf3[1][1], (sW + Qb2) ^ kx);
#pragma unroll
                for (int mt = 0; mt < 4; mt++) {
                    uint32_t a0, a1, a2, a3;
                    LDMX4(a0, a1, a2, a3, (sT + f.Qa[mt]) ^ kx);
#pragma unroll
                    for (int nt = 0; nt < 2; nt++)
                        mma_f16(acc3[mt][nt], a0, a1, a2, a3, bf3[nt][0], bf3[nt][1]);
                }
            }
        }

#pragma unroll
        for (int mt = 0; mt < 4; mt++) {
            int grow = b * NN + row0 + m_warp + mt * 16 + g;
            float m0 = mask[grow], m1 = mask[grow + 8];
#pragma unroll
            for (int nt = 0; nt < 2; nt++) {
                int col = n_warp2 + nt * 8 + 2 * tg;
                float pb0 = bproj[col], pb1 = bproj[col + 1];
                float2 p0, p1;
                p0.x = fmaf(acc3[mt][nt][0], UNSC2_F, pb0) * m0;
                p0.y = fmaf(acc3[mt][nt][1], UNSC2_F, pb1) * m0;
                p1.x = fmaf(acc3[mt][nt][2], UNSC2_F, pb0) * m1;
                p1.y = fmaf(acc3[mt][nt][3], UNSC2_F, pb1) * m1;
                *reinterpret_cast<float2*>(&out[(size_t)grow * OUTD + col])       = p0;
                *reinterpret_cast<float2*>(&out[(size_t)(grow + 8) * OUTD + col]) = p1;
            }
        }
    }
}

// ============================================================================
// Launch — fork-join DAG:
//   stream0: prep_all -> embed_mma ------\
//   stream2: conv_rowsum (28us, DRAM) ----+--> layer1 -> layer2 -> layer3(+proj)
// Stream/event create+destroy run host-side at capture time only; the captured
// graph contains the branched dependency structure.
// Inputs: 0 node_features [B,N,64] | 1 adjacency [B,N,N] | 2 node_mask [B,N,1]
//         3 W_embed [64,128] | 4 Wl [3,128,128] | 5 bl [3,128]
//         6 W_proj [128,64]  | 7 b_proj [64]      Output: [B,N,64] f32
// ============================================================================
extern "C" void kernel_launch(void* const* d_in, const int* in_sizes, int n_in,
                              void* d_out, int out_size)
{
    const float* x     = (const float*)d_in[0];
    const float* adj   = (const float*)d_in[1];
    const float* mask  = (const float*)d_in[2];
    const float* Wemb  = (const float*)d_in[3];
    const float* Wl    = (const float*)d_in[4];
    const float* bl    = (const float*)d_in[5];
    const float* Wproj = (const float*)d_in[6];
    const float* bproj = (const float*)d_in[7];
    float* out = (float*)d_out;

    __half *adjh = nullptr, *hT = nullptr, *wlt = nullptr;
    __half *xh = nullptr, *wembT = nullptr, *wpT = nullptr;
    float *rs = nullptr;
    cudaGetSymbolAddress((void**)&adjh,  g_adjh);
    cudaGetSymbolAddress((void**)&hT,    g_hT);
    cudaGetSymbolAddress((void**)&wlt,   g_WlTh);
    cudaGetSymbolAddress((void**)&xh,    g_xh);
    cudaGetSymbolAddress((void**)&wembT, g_WembTh);
    cudaGetSymbolAddress((void**)&wpT,   g_WprojTh);
    cudaGetSymbolAddress((void**)&rs,    g_rowsum);
    __half* hT0 = hT;
    __half* hT1 = hT + (size_t)BB * HID * NN;

    cudaFuncSetAttribute(adj_layer<false>,
                         cudaFuncAttributeMaxDynamicSharedMemorySize, SMTOT);
    cudaFuncSetAttribute(adj_layer<true>,
                         cudaFuncAttributeMaxDynamicSharedMemorySize, SMTOT);
    cudaFuncSetAttribute(embed_mma,
                         cudaFuncAttributeMaxDynamicSharedMemorySize, SMTOT_E);

    // Fork: conv_rowsum on side stream, prep+embed on main stream.
    cudaStream_t s2;
    cudaEvent_t evFork, evJoin;
    cudaStreamCreateWithFlags(&s2, cudaStreamNonBlocking);
    cudaEventCreateWithFlags(&evFork, cudaEventDisableTiming);
    cudaEventCreateWithFlags(&evJoin, cudaEventDisableTiming);

    cudaEventRecord(evFork, 0);
    cudaStreamWaitEvent(s2, evFork, 0);
    conv_rowsum<<<BB * NN / 8, 256, 0, s2>>>(adj, adjh, rs);
    cudaEventRecord(evJoin, s2);

    prep_all<<<NUM_LAYERS + 2 + CONVX_BLOCKS, 256>>>(
        Wl, Wemb, Wproj, x, wlt, wembT, wpT, xh);
    embed_mma<<<BB * NN / 128, 256, SMTOT_E>>>(xh, wembT, hT0);

    cudaStreamWaitEvent(0, evJoin, 0);   // join before layer 1

    dim3 bigg(NN / 128, BB);   // (8, 32)
    adj_layer<false><<<bigg, 256, SMTOT>>>(
        adjh, hT0, wlt,                 bl,           rs, hT1,
        nullptr, nullptr, nullptr, nullptr);
    adj_layer<false><<<bigg, 256, SMTOT>>>(
        adjh, hT1, wlt + HID * HID,     bl + HID,     rs, hT0,
        nullptr, nullptr, nullptr, nullptr);
    adj_layer<true><<<bigg, 256, SMTOT>>>(
        adjh, hT0, wlt + 2 * HID * HID, bl + 2 * HID, rs, nullptr,
        wpT, bproj, mask, out);

    cudaEventDestroy(evFork);
    cudaEventDestroy(evJoin);
    cudaStreamDestroy(s2);
}